// round 2
// baseline (speedup 1.0000x reference)
#include <cuda_runtime.h>
#include <cstddef>

#define N_USERS 200000
#define N_ITEMS 100000
#define N_NODES (N_USERS + N_ITEMS)
#define N_EDGES 4800000
#define EMB     64
#define BATCH   4096

// Scratch: per-node flag + per-node accumulator row (only ~8192 rows touched).
__device__ unsigned char g_flag[N_NODES];
__device__ float         g_acc[(size_t)N_NODES * EMB];

// ---------------------------------------------------------------------------
// Kernel 1: clear flags (300 KB)
// ---------------------------------------------------------------------------
__global__ void k_clear_flags() {
    int i = blockIdx.x * blockDim.x + threadIdx.x;
    // write 4 bytes at a time via int stores where possible
    if (i * 4 + 3 < N_NODES) {
        *reinterpret_cast<unsigned int*>(&g_flag[i * 4]) = 0u;
    } else if (i * 4 < N_NODES) {
        for (int b = i * 4; b < N_NODES; ++b) g_flag[b] = 0;
    }
}

// ---------------------------------------------------------------------------
// Kernel 2: mark needed nodes + zero their accumulator rows.
// 16 threads per output row (each zeroes one float4 of the 64-float row).
// Duplicate ids are benign (idempotent writes).
// ---------------------------------------------------------------------------
__global__ void k_mark(const int* __restrict__ uid, const int* __restrict__ iid) {
    int t = blockIdx.x * blockDim.x + threadIdx.x;
    int row = t >> 4;
    int j   = t & 15;
    if (row >= 2 * BATCH) return;
    int node = (row < BATCH) ? uid[row] : (N_USERS + iid[row - BATCH]);
    if (j == 0) g_flag[node] = 1;
    float4 z = make_float4(0.f, 0.f, 0.f, 0.f);
    *reinterpret_cast<float4*>(&g_acc[(size_t)node * EMB + j * 4]) = z;
}

// ---------------------------------------------------------------------------
// Kernel 3: edge scan. Each warp owns 32 consecutive edges. Lanes probe the
// flag for their edge's row; hits are processed warp-cooperatively:
// each lane handles 2 of the 64 embedding floats (coalesced float2 gather of
// x0[col], two float atomicAdds into acc[row]).
// ---------------------------------------------------------------------------
__global__ void k_edges(const int*   __restrict__ arow,
                        const int*   __restrict__ acol,
                        const float* __restrict__ avals,
                        const float* __restrict__ uemb,
                        const float* __restrict__ iemb) {
    long e    = (long)blockIdx.x * blockDim.x + threadIdx.x;
    int  lane = threadIdx.x & 31;
    long base = e - lane;

    int  r   = -1;
    bool hit = false;
    if (e < N_EDGES) {
        r   = arow[e];
        hit = (g_flag[r] != 0);
    }
    unsigned mask = __ballot_sync(0xffffffffu, hit);
    while (mask) {
        int src = __ffs(mask) - 1;
        mask &= mask - 1;
        int  rr = __shfl_sync(0xffffffffu, r, src);
        long ee = base + src;
        int   c = acol[ee];                 // all lanes same addr -> broadcast
        float v = avals[ee];
        const float* x = (c < N_USERS)
                       ? (uemb + (size_t)c * EMB)
                       : (iemb + (size_t)(c - N_USERS) * EMB);
        float2 xv = *reinterpret_cast<const float2*>(x + 2 * lane);
        float* a  = &g_acc[(size_t)rr * EMB + 2 * lane];
        atomicAdd(a,     v * xv.x);
        atomicAdd(a + 1, v * xv.y);
    }
}

// ---------------------------------------------------------------------------
// Kernel 4: output gather. out[0:4096) = z1[user_id], out[4096:8192) =
// z1[N_USERS + item_id], z1 = 2*x0 + acc. One thread per output element.
// ---------------------------------------------------------------------------
__global__ void k_out(const int*   __restrict__ uid,
                      const int*   __restrict__ iid,
                      const float* __restrict__ uemb,
                      const float* __restrict__ iemb,
                      float*       __restrict__ out) {
    int t = blockIdx.x * blockDim.x + threadIdx.x;
    if (t >= 2 * BATCH * EMB) return;
    int row = t >> 6;          // output row 0..8191
    int k   = t & 63;
    int node = (row < BATCH) ? uid[row] : (N_USERS + iid[row - BATCH]);
    const float* x = (node < N_USERS)
                   ? (uemb + (size_t)node * EMB)
                   : (iemb + (size_t)(node - N_USERS) * EMB);
    out[t] = 2.0f * x[k] + g_acc[(size_t)node * EMB + k];
}

// ---------------------------------------------------------------------------
extern "C" void kernel_launch(void* const* d_in, const int* in_sizes, int n_in,
                              void* d_out, int out_size) {
    const float* uemb  = (const float*)d_in[0];
    const float* iemb  = (const float*)d_in[1];
    const int*   arow  = (const int*)  d_in[2];
    const int*   acol  = (const int*)  d_in[3];
    const float* avals = (const float*)d_in[4];
    const int*   uid   = (const int*)  d_in[5];
    const int*   iid   = (const int*)  d_in[6];
    float*       out   = (float*)      d_out;

    {
        int n = (N_NODES + 3) / 4;                       // 4 bytes per thread
        k_clear_flags<<<(n + 255) / 256, 256>>>();
    }
    {
        int n = 2 * BATCH * 16;
        k_mark<<<(n + 255) / 256, 256>>>(uid, iid);
    }
    {
        int n = N_EDGES;
        k_edges<<<(n + 255) / 256, 256>>>(arow, acol, avals, uemb, iemb);
    }
    {
        int n = 2 * BATCH * EMB;
        k_out<<<(n + 255) / 256, 256>>>(uid, iid, uemb, iemb, out);
    }
}

// round 4
// speedup vs baseline: 1.3774x; 1.3774x over previous
#include <cuda_runtime.h>
#include <cstddef>

#define N_USERS 200000
#define N_ITEMS 100000
#define N_NODES (N_USERS + N_ITEMS)
#define N_EDGES 4800000
#define EMB     64
#define BATCH   4096
#define NBITW   ((N_NODES + 31) / 32)

// Scratch. Zero-initialized at module load; every launch leaves g_bits zeroed
// (k_out clears the words of all marked nodes) so replays start clean.
__device__ unsigned int g_bits[NBITW];                 // 37.5 KB node bitmask
__device__ float        g_acc[(size_t)N_NODES * EMB];  // only marked rows touched

// ---------------------------------------------------------------------------
// Kernel 1: mark needed nodes (atomicOr into bitmask) + zero their acc rows.
// 16 threads per output row, one float4 each. Duplicate ids are idempotent.
// ---------------------------------------------------------------------------
__global__ void k_mark(const int* __restrict__ uid, const int* __restrict__ iid) {
    int t = blockIdx.x * blockDim.x + threadIdx.x;
    if (t >= 2 * BATCH * 16) return;
    int row = t >> 4;
    int j   = t & 15;
    int node = (row < BATCH) ? uid[row] : (N_USERS + iid[row - BATCH]);
    if (j == 0) atomicOr(&g_bits[node >> 5], 1u << (node & 31));
    *reinterpret_cast<float4*>(&g_acc[(size_t)node * EMB + j * 4]) =
        make_float4(0.f, 0.f, 0.f, 0.f);
}

// ---------------------------------------------------------------------------
// Kernel 2: edge scan. Each thread owns 4 consecutive edges (int4 load of
// adj_row), probes the L1-resident bitmask; hits are processed
// warp-cooperatively: each lane handles 2 of the 64 embedding floats
// (coalesced float2 gather of x0[col] + 2 atomicAdds into acc[row]).
// ---------------------------------------------------------------------------
__global__ void k_edges(const int*   __restrict__ arow,
                        const int*   __restrict__ acol,
                        const float* __restrict__ avals,
                        const float* __restrict__ uemb,
                        const float* __restrict__ iemb) {
    int t    = blockIdx.x * blockDim.x + threadIdx.x;
    int lane = threadIdx.x & 31;
    bool valid = (t * 4 < N_EDGES);   // N_EDGES % 4 == 0

    int4 r4 = make_int4(0, 0, 0, 0);
    if (valid) r4 = reinterpret_cast<const int4*>(arow)[t];
    int rr[4] = {r4.x, r4.y, r4.z, r4.w};

    long base = (long)(t - lane);     // first thread of this warp

    #pragma unroll
    for (int j = 0; j < 4; ++j) {
        int  r   = rr[j];
        bool hit = valid && ((g_bits[r >> 5] >> (r & 31)) & 1u);
        unsigned m = __ballot_sync(0xffffffffu, hit);
        while (m) {
            int src = __ffs(m) - 1;
            m &= m - 1;
            int  row = __shfl_sync(0xffffffffu, r, src);
            long ee  = 4L * (base + src) + j;
            int   c = __ldg(&acol[ee]);     // same addr warp-wide -> broadcast
            float v = __ldg(&avals[ee]);
            const float* x = (c < N_USERS)
                           ? (uemb + (size_t)c * EMB)
                           : (iemb + (size_t)(c - N_USERS) * EMB);
            float2 xv = *reinterpret_cast<const float2*>(x + 2 * lane);
            float* a  = &g_acc[(size_t)row * EMB + 2 * lane];
            atomicAdd(a,     v * xv.x);
            atomicAdd(a + 1, v * xv.y);
        }
    }
}

// ---------------------------------------------------------------------------
// Kernel 3: output gather + bitmask cleanup.
// out[0:4096) = z1[user_id], out[4096:8192) = z1[N_USERS + item_id],
// z1 = 2*x0 + acc. 16 threads per row, one float4 each.
// j==0 thread clears the node's bit-word (leaves g_bits all-zero for the
// next launch; words not containing marked bits are already zero).
// ---------------------------------------------------------------------------
__global__ void k_out(const int*   __restrict__ uid,
                      const int*   __restrict__ iid,
                      const float* __restrict__ uemb,
                      const float* __restrict__ iemb,
                      float*       __restrict__ out) {
    int t = blockIdx.x * blockDim.x + threadIdx.x;
    if (t >= 2 * BATCH * 16) return;
    int row = t >> 4;
    int j   = t & 15;
    int node = (row < BATCH) ? uid[row] : (N_USERS + iid[row - BATCH]);
    if (j == 0) g_bits[node >> 5] = 0u;
    const float* x = (node < N_USERS)
                   ? (uemb + (size_t)node * EMB)
                   : (iemb + (size_t)(node - N_USERS) * EMB);
    float4 xv = *reinterpret_cast<const float4*>(x + 4 * j);
    float4 av = *reinterpret_cast<const float4*>(&g_acc[(size_t)node * EMB + 4 * j]);
    float4 o;
    o.x = 2.0f * xv.x + av.x;
    o.y = 2.0f * xv.y + av.y;
    o.z = 2.0f * xv.z + av.z;
    o.w = 2.0f * xv.w + av.w;
    *reinterpret_cast<float4*>(&out[(size_t)row * EMB + 4 * j]) = o;
}

// ---------------------------------------------------------------------------
extern "C" void kernel_launch(void* const* d_in, const int* in_sizes, int n_in,
                              void* d_out, int out_size) {
    const float* uemb  = (const float*)d_in[0];
    const float* iemb  = (const float*)d_in[1];
    const int*   arow  = (const int*)  d_in[2];
    const int*   acol  = (const int*)  d_in[3];
    const float* avals = (const float*)d_in[4];
    const int*   uid   = (const int*)  d_in[5];
    const int*   iid   = (const int*)  d_in[6];
    float*       out   = (float*)      d_out;

    {
        int n = 2 * BATCH * 16;                    // 131072
        k_mark<<<(n + 255) / 256, 256>>>(uid, iid);
    }
    {
        int n = N_EDGES / 4;                       // 1.2M threads
        k_edges<<<(n + 255) / 256, 256>>>(arow, acol, avals, uemb, iemb);
    }
    {
        int n = 2 * BATCH * 16;                    // 131072
        k_out<<<(n + 255) / 256, 256>>>(uid, iid, uemb, iemb, out);
    }
}